// round 1
// baseline (speedup 1.0000x reference)
#include <cuda_runtime.h>
#include <cuda_bf16.h>
#include <math.h>

#define BS 16
#define Q 900
#define NC 92
#define TPB 100          // targets per batch
#define NT 1600          // total targets
#define C_ELEMS (16*900*1600)  // 23040000

// transposed per-batch cost slice: ctr[b][t][q], t in [0,100), q in [0,900)
__device__ float g_ctr[BS * TPB * Q];
__device__ int   g_idmode;   // 1 => tgt_ids stored as int64, 0 => int32

// ---------------------------------------------------------------------------
// Detect whether tgt_ids buffer is int64 or int32. Reads only the first 6400
// bytes (valid in both layouts). All ids are in [0,92).
// ---------------------------------------------------------------------------
__global__ void detect_ids_kernel(const unsigned int* __restrict__ ids)
{
    int ok64 = 1;
    for (int k = 0; k < 800; k++) {
        unsigned lo = ids[2*k], hi = ids[2*k+1];
        if (hi != 0u || lo >= 92u) { ok64 = 0; break; }
    }
    g_idmode = ok64;
}

// ---------------------------------------------------------------------------
// Cost matrix kernel: 8 queries per block, 128 threads.
// Stages all 1600 targets in SMEM once per block.
// ---------------------------------------------------------------------------
#define QPB 8
__global__ void cost_kernel(const float* __restrict__ logits,
                            const float* __restrict__ boxes,
                            const void*  __restrict__ ids,
                            const float* __restrict__ tbox,
                            float* __restrict__ C)
{
    __shared__ float4 s_tb[NT];          // xyxy target boxes
    __shared__ int    s_id[NT];
    __shared__ float  s_prob[QPB][NC];
    __shared__ float  s_box[QPB][4];

    const int tid = threadIdx.x;         // 128
    const int base_bq = blockIdx.x * QPB;
    const int mode = g_idmode;

    // stage targets
    const float4* tb4 = (const float4*)tbox;
    for (int x = tid; x < NT; x += 128) s_tb[x] = tb4[x];
    if (mode) {
        const long long* id64 = (const long long*)ids;
        for (int x = tid; x < NT; x += 128) s_id[x] = (int)id64[x];
    } else {
        const int* id32 = (const int*)ids;
        for (int x = tid; x < NT; x += 128) s_id[x] = id32[x];
    }

    // softmax: warp w handles queries r = w, w+4
    const int w = tid >> 5, lane = tid & 31;
    for (int r = w; r < QPB; r += 4) {
        int bq = base_bq + r;
        const float* lr = logits + (size_t)bq * NC;
        float x0 = lr[lane];
        float x1 = lr[lane + 32];
        float x2 = (lane + 64 < NC) ? lr[lane + 64] : -1e30f;
        float m = fmaxf(x0, fmaxf(x1, x2));
        for (int o = 16; o; o >>= 1) m = fmaxf(m, __shfl_xor_sync(~0u, m, o));
        float e0 = expf(x0 - m);
        float e1 = expf(x1 - m);
        float e2 = (lane + 64 < NC) ? expf(x2 - m) : 0.0f;
        float s = e0 + e1 + e2;
        for (int o = 16; o; o >>= 1) s += __shfl_xor_sync(~0u, s, o);
        float inv = 1.0f / s;
        s_prob[r][lane]      = e0 * inv;
        s_prob[r][lane + 32] = e1 * inv;
        if (lane + 64 < NC) s_prob[r][lane + 64] = e2 * inv;
        if (lane < 4) s_box[r][lane] = boxes[(size_t)bq * 4 + lane];
    }
    __syncthreads();

    for (int r = 0; r < QPB; r++) {
        const int bq = base_bq + r;
        const int b = bq / Q;
        const int q = bq - b * Q;
        const float pcx = s_box[r][0], pcy = s_box[r][1];
        const float pw  = s_box[r][2], ph  = s_box[r][3];
        const float px0 = pcx - pw * 0.5f, py0 = pcy - ph * 0.5f;
        const float px1 = pcx + pw * 0.5f, py1 = pcy + ph * 0.5f;
        const float pa  = (px1 - px0) * (py1 - py0);
        float* Crow = C + (size_t)bq * NT;
        const int jlo = b * TPB, jhi = jlo + TPB;
        for (int j = tid; j < NT; j += 128) {
            float4 t = s_tb[j];
            float tx0 = t.x, ty0 = t.y, tx1 = t.z, ty1 = t.w;
            float tcx = (tx0 + tx1) * 0.5f, tcy = (ty0 + ty1) * 0.5f;
            float tw = tx1 - tx0, th = ty1 - ty0;
            float cbb = fabsf(pcx - tcx) + fabsf(pcy - tcy)
                      + fabsf(pw - tw) + fabsf(ph - th);
            float ta = tw * th;
            float ix0 = fmaxf(px0, tx0), iy0 = fmaxf(py0, ty0);
            float ix1 = fminf(px1, tx1), iy1 = fminf(py1, ty1);
            float iw = fmaxf(ix1 - ix0, 0.0f), ih = fmaxf(iy1 - iy0, 0.0f);
            float inter = iw * ih;
            float uni = pa + ta - inter;
            float iou = inter / uni;
            float ex0 = fminf(px0, tx0), ey0 = fminf(py0, ty0);
            float ex1 = fmaxf(px1, tx1), ey1 = fmaxf(py1, ty1);
            float cw = fmaxf(ex1 - ex0, 0.0f), ch = fmaxf(ey1 - ey0, 0.0f);
            float ca = cw * ch;
            float giou = iou - (ca - uni) / ca;
            float val = 5.0f * cbb - s_prob[r][s_id[j]] - 2.0f * giou;
            Crow[j] = val;
            if (j >= jlo && j < jhi)
                g_ctr[b * (TPB * Q) + (j - jlo) * Q + q] = val;
        }
    }
}

// ---------------------------------------------------------------------------
// Hungarian (JV shortest augmenting path) per batch. One block per batch.
// Exactly mirrors the reference's float64 dual arithmetic so the assignment
// matches bitwise.
// ---------------------------------------------------------------------------
__global__ void __launch_bounds__(256, 1) lsa_kernel(float* __restrict__ out)
{
    const int b = blockIdx.x;
    const int tid = threadIdx.x;  // 256; column slots j = 1 + tid + k*256

    __shared__ double u[TPB + 4];
    __shared__ int    p[Q + 4];
    __shared__ int    way[Q + 4];
    __shared__ double s_wmin[8];
    __shared__ int    s_wj[8];
    __shared__ double s_delta;
    __shared__ int    s_j0, s_j1, s_done;
    __shared__ int    ans[TPB];

    double minv[4], v[4];
    int used_m;

    for (int x = tid; x <= Q; x += 256) p[x] = 0;
    for (int x = tid; x <= TPB; x += 256) u[x] = 0.0;
#pragma unroll
    for (int k = 0; k < 4; k++) v[k] = 0.0;
    __syncthreads();

    const float* cb = g_ctr + b * (TPB * Q);

    for (int i = 1; i <= TPB; i++) {
        if (tid == 0) { p[0] = i; s_j0 = 0; }
#pragma unroll
        for (int k = 0; k < 4; k++) minv[k] = 1e300;
        used_m = 0;
        __syncthreads();

        while (true) {
            const int j0 = s_j0;
            const int i0 = p[j0];
            const double ui0 = u[i0];
            // mark used (register-owned)
            if (j0 >= 1) {
                int idx = j0 - 1;
                if ((idx & 255) == tid) used_m |= 1 << (idx >> 8);
            }
            const float* crow = cb + (i0 - 1) * Q;
            double lmin = 1e300; int lj = Q + 2;
#pragma unroll
            for (int k = 0; k < 4; k++) {
                int j = 1 + tid + k * 256;
                if (j <= Q && !((used_m >> k) & 1)) {
                    double cur = ((double)crow[j - 1] - ui0) - v[k];
                    if (cur < minv[k]) { minv[k] = cur; way[j] = j0; }
                    if (minv[k] < lmin) { lmin = minv[k]; lj = j; }
                }
            }
            // reduce (lmin, lj), ties -> smaller j
            for (int o = 16; o; o >>= 1) {
                double om = __shfl_xor_sync(~0u, lmin, o);
                int    oj = __shfl_xor_sync(~0u, lj, o);
                if (om < lmin || (om == lmin && oj < lj)) { lmin = om; lj = oj; }
            }
            if ((tid & 31) == 0) { s_wmin[tid >> 5] = lmin; s_wj[tid >> 5] = lj; }
            __syncthreads();
            if (tid == 0) {
                double dm = s_wmin[0]; int dj = s_wj[0];
                for (int ww = 1; ww < 8; ww++) {
                    if (s_wmin[ww] < dm || (s_wmin[ww] == dm && s_wj[ww] < dj)) {
                        dm = s_wmin[ww]; dj = s_wj[ww];
                    }
                }
                s_delta = dm; s_j1 = dj; s_j0 = dj;
                s_done = (p[dj] == 0);
            }
            __syncthreads();
            const double delta = s_delta;
            const int j1 = s_j1;
            const int done = s_done;
#pragma unroll
            for (int k = 0; k < 4; k++) {
                int j = 1 + tid + k * 256;
                if (j <= Q) {
                    if ((used_m >> k) & 1) { v[k] -= delta; u[p[j]] += delta; }
                    else                    minv[k] -= delta;
                }
            }
            if (tid == 0) u[p[0]] += delta;   // virtual column 0 (always used)
            __syncthreads();
            if (done) {
                if (tid == 0) {
                    int jj = j1;
                    while (jj) { int jp = way[jj]; p[jj] = p[jp]; jj = jp; }
                }
                __syncthreads();
                break;
            }
        }
    }

    // ans[t] = matched prediction index for target t
#pragma unroll
    for (int k = 0; k < 4; k++) {
        int j = 1 + tid + k * 256;
        if (j <= Q && p[j] > 0) ans[p[j] - 1] = j - 1;
    }
    __syncthreads();
    // rows = sorted pred indices, cols = corresponding target indices
    if (tid < TPB) {
        int a = ans[tid];
        int rank = 0;
        for (int t2 = 0; t2 < TPB; t2++) rank += (ans[t2] < a) ? 1 : 0;
        out[(size_t)C_ELEMS + (size_t)b * TPB + rank]            = (float)a;
        out[(size_t)C_ELEMS + (size_t)BS * TPB + (size_t)b * TPB + rank] = (float)tid;
    }
}

// ---------------------------------------------------------------------------
extern "C" void kernel_launch(void* const* d_in, const int* in_sizes, int n_in,
                              void* d_out, int out_size)
{
    const float* logits = (const float*)d_in[0];
    const float* boxes  = (const float*)d_in[1];
    const void*  ids    = d_in[2];
    const float* tbox   = (const float*)d_in[3];
    float* out = (float*)d_out;

    detect_ids_kernel<<<1, 1>>>((const unsigned int*)ids);
    cost_kernel<<<(BS * Q) / QPB, 128>>>(logits, boxes, ids, tbox, out);
    lsa_kernel<<<BS, 256>>>(out);
}

// round 2
// speedup vs baseline: 1.0199x; 1.0199x over previous
#include <cuda_runtime.h>
#include <cuda_bf16.h>
#include <math.h>

#define BS 16
#define Q 900
#define NC 92
#define TPB 100          // targets per batch
#define NT 1600          // total targets
#define C_ELEMS (16*900*1600)  // 23040000

// transposed per-batch cost slice: ctr[b][t][q], t in [0,100), q in [0,900)
__device__ float g_ctr[BS * TPB * Q];
__device__ int   g_idmode;   // 1 => tgt_ids stored as int64, 0 => int32

// ---------------------------------------------------------------------------
// Detect whether tgt_ids buffer is int64 or int32. Reads only the first 6400
// bytes (valid in both layouts). All ids are in [0,92).
// ---------------------------------------------------------------------------
__global__ void detect_ids_kernel(const unsigned int* __restrict__ ids)
{
    int ok64 = 1;
    for (int k = 0; k < 800; k++) {
        unsigned lo = ids[2*k], hi = ids[2*k+1];
        if (hi != 0u || lo >= 92u) { ok64 = 0; break; }
    }
    g_idmode = ok64;
}

// ---------------------------------------------------------------------------
// Cost matrix kernel: 8 queries per block, 128 threads.
// Stages all 1600 targets in SMEM once per block. Coalesced C writes only.
// ---------------------------------------------------------------------------
#define QPB 8
__global__ void cost_kernel(const float* __restrict__ logits,
                            const float* __restrict__ boxes,
                            const void*  __restrict__ ids,
                            const float* __restrict__ tbox,
                            float* __restrict__ C)
{
    __shared__ float4 s_tb[NT];          // xyxy target boxes
    __shared__ int    s_id[NT];
    __shared__ float  s_prob[QPB][NC];
    __shared__ float  s_box[QPB][4];

    const int tid = threadIdx.x;         // 128
    const int base_bq = blockIdx.x * QPB;
    const int mode = g_idmode;

    // stage targets
    const float4* tb4 = (const float4*)tbox;
    for (int x = tid; x < NT; x += 128) s_tb[x] = tb4[x];
    if (mode) {
        const long long* id64 = (const long long*)ids;
        for (int x = tid; x < NT; x += 128) s_id[x] = (int)id64[x];
    } else {
        const int* id32 = (const int*)ids;
        for (int x = tid; x < NT; x += 128) s_id[x] = id32[x];
    }

    // softmax: warp w handles queries r = w, w+4
    const int w = tid >> 5, lane = tid & 31;
    for (int r = w; r < QPB; r += 4) {
        int bq = base_bq + r;
        const float* lr = logits + (size_t)bq * NC;
        float x0 = lr[lane];
        float x1 = lr[lane + 32];
        float x2 = (lane + 64 < NC) ? lr[lane + 64] : -1e30f;
        float m = fmaxf(x0, fmaxf(x1, x2));
        for (int o = 16; o; o >>= 1) m = fmaxf(m, __shfl_xor_sync(~0u, m, o));
        float e0 = expf(x0 - m);
        float e1 = expf(x1 - m);
        float e2 = (lane + 64 < NC) ? expf(x2 - m) : 0.0f;
        float s = e0 + e1 + e2;
        for (int o = 16; o; o >>= 1) s += __shfl_xor_sync(~0u, s, o);
        float inv = 1.0f / s;
        s_prob[r][lane]      = e0 * inv;
        s_prob[r][lane + 32] = e1 * inv;
        if (lane + 64 < NC) s_prob[r][lane + 64] = e2 * inv;
        if (lane < 4) s_box[r][lane] = boxes[(size_t)bq * 4 + lane];
    }
    __syncthreads();

    for (int r = 0; r < QPB; r++) {
        const int bq = base_bq + r;
        const float pcx = s_box[r][0], pcy = s_box[r][1];
        const float pw  = s_box[r][2], ph  = s_box[r][3];
        const float px0 = pcx - pw * 0.5f, py0 = pcy - ph * 0.5f;
        const float px1 = pcx + pw * 0.5f, py1 = pcy + ph * 0.5f;
        const float pa  = (px1 - px0) * (py1 - py0);
        float* Crow = C + (size_t)bq * NT;
        for (int j = tid; j < NT; j += 128) {
            float4 t = s_tb[j];
            float tx0 = t.x, ty0 = t.y, tx1 = t.z, ty1 = t.w;
            float tcx = (tx0 + tx1) * 0.5f, tcy = (ty0 + ty1) * 0.5f;
            float tw = tx1 - tx0, th = ty1 - ty0;
            float cbb = fabsf(pcx - tcx) + fabsf(pcy - tcy)
                      + fabsf(pw - tw) + fabsf(ph - th);
            float ta = tw * th;
            float ix0 = fmaxf(px0, tx0), iy0 = fmaxf(py0, ty0);
            float ix1 = fminf(px1, tx1), iy1 = fminf(py1, ty1);
            float iw = fmaxf(ix1 - ix0, 0.0f), ih = fmaxf(iy1 - iy0, 0.0f);
            float inter = iw * ih;
            float uni = pa + ta - inter;
            float iou = inter / uni;
            float ex0 = fminf(px0, tx0), ey0 = fminf(py0, ty0);
            float ex1 = fmaxf(px1, tx1), ey1 = fmaxf(py1, ty1);
            float cw = fmaxf(ex1 - ex0, 0.0f), ch = fmaxf(ey1 - ey0, 0.0f);
            float ca = cw * ch;
            float giou = iou - (ca - uni) / ca;
            float val = 5.0f * cbb - s_prob[r][s_id[j]] - 2.0f * giou;
            Crow[j] = val;
        }
    }
}

// ---------------------------------------------------------------------------
// Transpose kernel: extract per-batch slice C[b, q, b*T + t] -> g_ctr[b][t][q]
// 32x32 SMEM tiles; fully coalesced on both sides.
// ---------------------------------------------------------------------------
__global__ void transpose_kernel(const float* __restrict__ C)
{
    __shared__ float tile[32][33];
    const int b  = blockIdx.z;
    const int q0 = blockIdx.x * 32;
    const int t0 = blockIdx.y * 32;
    int q = q0 + threadIdx.y;
    int t = t0 + threadIdx.x;
    if (q < Q && t < TPB)
        tile[threadIdx.y][threadIdx.x] =
            C[((size_t)(b * Q + q)) * NT + (size_t)b * TPB + t];
    __syncthreads();
    int tt = t0 + threadIdx.y;
    int qq = q0 + threadIdx.x;
    if (tt < TPB && qq < Q)
        g_ctr[b * (TPB * Q) + tt * Q + qq] = tile[threadIdx.x][threadIdx.y];
}

// ---------------------------------------------------------------------------
// Hungarian (JV shortest augmenting path) per batch. One block per batch.
// Mirrors the reference's float64 dual arithmetic exactly (same op order,
// smallest-j tie-break). 2 block barriers per inner iteration; next row's
// cost loads + u[i1] are prefetched across the update phase and barrier.
// ---------------------------------------------------------------------------
__global__ void __launch_bounds__(256, 1) lsa_kernel(float* __restrict__ out)
{
    const int b = blockIdx.x;
    const int tid = threadIdx.x;  // 256; column slots j = 1 + tid + k*256

    __shared__ double u[TPB + 2];
    __shared__ int    p[Q + 2];
    __shared__ int    way[Q + 2];
    __shared__ double s_wmin[8];
    __shared__ int    s_wj[8];
    __shared__ int    ans[TPB];

    double v[4];
    int jcol[4];
#pragma unroll
    for (int k = 0; k < 4; k++) { v[k] = 0.0; jcol[k] = 1 + tid + k * 256; }

    for (int x = tid; x <= Q; x += 256) p[x] = 0;
    for (int x = tid; x <= TPB; x += 256) u[x] = 0.0;
    __syncthreads();

    const float* cb = g_ctr + b * (TPB * Q);

    for (int i = 1; i <= TPB; i++) {
        if (tid == 0) p[0] = i;
        double minv[4];
        int usedm = 0;
        int rowof[4];
#pragma unroll
        for (int k = 0; k < 4; k++) { minv[k] = 1e300; rowof[k] = 0; }

        int i0 = i, j0 = 0;
        double ui0 = 0.0;   // u[i] == 0 when row i starts (never matched before)
        float r[4];
        {
            const float* crow = cb + (i0 - 1) * Q;
#pragma unroll
            for (int k = 0; k < 4; k++)
                r[k] = (jcol[k] <= Q) ? __ldg(&crow[jcol[k] - 1]) : 0.0f;
        }

        while (true) {
            // mark column chosen last iteration as used; cache its row
            if (j0 >= 1) {
                int idx = j0 - 1;
                if ((idx & 255) == tid) {
                    usedm |= 1 << (idx >> 8);
                    rowof[idx >> 8] = i0;
                }
            }
            // candidate scan over my unused columns
            double lmin = 1e300; int lj = Q + 2;
#pragma unroll
            for (int k = 0; k < 4; k++) {
                if (jcol[k] <= Q && !((usedm >> k) & 1)) {
                    double cur = ((double)r[k] - ui0) - v[k];
                    if (cur < minv[k]) { minv[k] = cur; way[jcol[k]] = j0; }
                    if (minv[k] < lmin) { lmin = minv[k]; lj = jcol[k]; }
                }
            }
            // warp reduce (ties -> smaller j)
            for (int o = 16; o; o >>= 1) {
                double om = __shfl_xor_sync(~0u, lmin, o);
                int    oj = __shfl_xor_sync(~0u, lj, o);
                if (om < lmin || (om == lmin && oj < lj)) { lmin = om; lj = oj; }
            }
            if ((tid & 31) == 0) { s_wmin[tid >> 5] = lmin; s_wj[tid >> 5] = lj; }
            __syncthreads();                                   // B1

            // all threads compute the final reduce redundantly
            double delta = s_wmin[0]; int j1 = s_wj[0];
#pragma unroll
            for (int ww = 1; ww < 8; ww++) {
                double m2 = s_wmin[ww]; int j2 = s_wj[ww];
                if (m2 < delta || (m2 == delta && j2 < j1)) { delta = m2; j1 = j2; }
            }
            const int i1 = p[j1];

            // prefetch next row + next u across the update phase and B2.
            // Safe: u[i1] is NOT modified this iteration (i1 not in any used column).
            float r2[4]; double unext = 0.0;
            if (i1 != 0) {
                const float* crow2 = cb + (i1 - 1) * Q;
#pragma unroll
                for (int k = 0; k < 4; k++)
                    r2[k] = (jcol[k] <= Q) ? __ldg(&crow2[jcol[k] - 1]) : 0.0f;
                unext = u[i1];
            }

            // dual updates (reference order: u[p[used]] += delta; v[used] -= delta;
            // minv[unused] -= delta)
#pragma unroll
            for (int k = 0; k < 4; k++) {
                if (jcol[k] <= Q) {
                    if ((usedm >> k) & 1) { v[k] -= delta; u[rowof[k]] += delta; }
                    else                    minv[k] -= delta;
                }
            }
            if (tid == 0) u[i] += delta;   // column 0 (always used, row = i)
            __syncthreads();                                   // B2

            if (i1 == 0) {
                if (tid == 0) {
                    int jj = j1;
                    while (jj) { int jp = way[jj]; p[jj] = p[jp]; jj = jp; }
                }
                break;
            }
            j0 = j1; i0 = i1; ui0 = unext;
#pragma unroll
            for (int k = 0; k < 4; k++) r[k] = r2[k];
        }
        __syncthreads();   // path-walk p[] writes visible to next augmentation
    }

    // ans[t] = matched prediction index for target t
#pragma unroll
    for (int k = 0; k < 4; k++) {
        int j = jcol[k];
        if (j <= Q && p[j] > 0) ans[p[j] - 1] = j - 1;
    }
    __syncthreads();
    // rows = sorted pred indices, cols = corresponding target indices
    if (tid < TPB) {
        int a = ans[tid];
        int rank = 0;
        for (int t2 = 0; t2 < TPB; t2++) rank += (ans[t2] < a) ? 1 : 0;
        out[(size_t)C_ELEMS + (size_t)b * TPB + rank]                    = (float)a;
        out[(size_t)C_ELEMS + (size_t)BS * TPB + (size_t)b * TPB + rank] = (float)tid;
    }
}

// ---------------------------------------------------------------------------
extern "C" void kernel_launch(void* const* d_in, const int* in_sizes, int n_in,
                              void* d_out, int out_size)
{
    const float* logits = (const float*)d_in[0];
    const float* boxes  = (const float*)d_in[1];
    const void*  ids    = d_in[2];
    const float* tbox   = (const float*)d_in[3];
    float* out = (float*)d_out;

    detect_ids_kernel<<<1, 1>>>((const unsigned int*)ids);
    cost_kernel<<<(BS * Q) / QPB, 128>>>(logits, boxes, ids, tbox, out);
    dim3 tgrid((Q + 31) / 32, (TPB + 31) / 32, BS);
    transpose_kernel<<<tgrid, dim3(32, 32)>>>(out);
    lsa_kernel<<<BS, 256>>>(out);
}

// round 3
// speedup vs baseline: 1.1171x; 1.0954x over previous
#include <cuda_runtime.h>
#include <cuda_bf16.h>
#include <math.h>

#define BS 16
#define Q 900
#define NC 92
#define TPB 100          // targets per batch
#define NT 1600          // total targets
#define C_ELEMS (16*900*1600)  // 23040000

// transposed per-batch cost slice: ctr[b][t][q]
__device__ float g_ctr[BS * TPB * Q];
__device__ int   g_idmode;   // 1 => tgt_ids stored as int64, 0 => int32

// ---------------------------------------------------------------------------
// Detect whether tgt_ids buffer is int64 or int32 (parallel, 1 warp-group).
// ---------------------------------------------------------------------------
__global__ void detect_ids_kernel(const unsigned int* __restrict__ ids)
{
    const int tid = threadIdx.x;  // 128
    int ok = 1;
    for (int k = tid; k < 800; k += 128) {
        unsigned lo = ids[2*k], hi = ids[2*k+1];
        if (hi != 0u || lo >= 92u) ok = 0;
    }
    ok = __syncthreads_and(ok);
    if (tid == 0) g_idmode = ok;
}

// ---------------------------------------------------------------------------
// Cost matrix kernel: 8 queries per block, 128 threads.
// ---------------------------------------------------------------------------
#define QPB 8
__global__ void cost_kernel(const float* __restrict__ logits,
                            const float* __restrict__ boxes,
                            const void*  __restrict__ ids,
                            const float* __restrict__ tbox,
                            float* __restrict__ C)
{
    __shared__ float4 s_tb[NT];          // xyxy target boxes
    __shared__ int    s_id[NT];
    __shared__ float  s_prob[QPB][NC];
    __shared__ float  s_box[QPB][4];

    const int tid = threadIdx.x;         // 128
    const int base_bq = blockIdx.x * QPB;
    const int mode = g_idmode;

    const float4* tb4 = (const float4*)tbox;
    for (int x = tid; x < NT; x += 128) s_tb[x] = tb4[x];
    if (mode) {
        const long long* id64 = (const long long*)ids;
        for (int x = tid; x < NT; x += 128) s_id[x] = (int)id64[x];
    } else {
        const int* id32 = (const int*)ids;
        for (int x = tid; x < NT; x += 128) s_id[x] = id32[x];
    }

    const int w = tid >> 5, lane = tid & 31;
    for (int r = w; r < QPB; r += 4) {
        int bq = base_bq + r;
        const float* lr = logits + (size_t)bq * NC;
        float x0 = lr[lane];
        float x1 = lr[lane + 32];
        float x2 = (lane + 64 < NC) ? lr[lane + 64] : -1e30f;
        float m = fmaxf(x0, fmaxf(x1, x2));
        for (int o = 16; o; o >>= 1) m = fmaxf(m, __shfl_xor_sync(~0u, m, o));
        float e0 = expf(x0 - m);
        float e1 = expf(x1 - m);
        float e2 = (lane + 64 < NC) ? expf(x2 - m) : 0.0f;
        float s = e0 + e1 + e2;
        for (int o = 16; o; o >>= 1) s += __shfl_xor_sync(~0u, s, o);
        float inv = 1.0f / s;
        s_prob[r][lane]      = e0 * inv;
        s_prob[r][lane + 32] = e1 * inv;
        if (lane + 64 < NC) s_prob[r][lane + 64] = e2 * inv;
        if (lane < 4) s_box[r][lane] = boxes[(size_t)bq * 4 + lane];
    }
    __syncthreads();

    for (int r = 0; r < QPB; r++) {
        const int bq = base_bq + r;
        const float pcx = s_box[r][0], pcy = s_box[r][1];
        const float pw  = s_box[r][2], ph  = s_box[r][3];
        const float px0 = pcx - pw * 0.5f, py0 = pcy - ph * 0.5f;
        const float px1 = pcx + pw * 0.5f, py1 = pcy + ph * 0.5f;
        const float pa  = (px1 - px0) * (py1 - py0);
        float* Crow = C + (size_t)bq * NT;
        for (int j = tid; j < NT; j += 128) {
            float4 t = s_tb[j];
            float tx0 = t.x, ty0 = t.y, tx1 = t.z, ty1 = t.w;
            float tcx = (tx0 + tx1) * 0.5f, tcy = (ty0 + ty1) * 0.5f;
            float tw = tx1 - tx0, th = ty1 - ty0;
            float cbb = fabsf(pcx - tcx) + fabsf(pcy - tcy)
                      + fabsf(pw - tw) + fabsf(ph - th);
            float ta = tw * th;
            float ix0 = fmaxf(px0, tx0), iy0 = fmaxf(py0, ty0);
            float ix1 = fminf(px1, tx1), iy1 = fminf(py1, ty1);
            float iw = fmaxf(ix1 - ix0, 0.0f), ih = fmaxf(iy1 - iy0, 0.0f);
            float inter = iw * ih;
            float uni = pa + ta - inter;
            float iou = inter / uni;
            float ex0 = fminf(px0, tx0), ey0 = fminf(py0, ty0);
            float ex1 = fmaxf(px1, tx1), ey1 = fmaxf(py1, ty1);
            float cw = fmaxf(ex1 - ex0, 0.0f), ch = fmaxf(ey1 - ey0, 0.0f);
            float ca = cw * ch;
            float giou = iou - (ca - uni) / ca;
            float val = 5.0f * cbb - s_prob[r][s_id[j]] - 2.0f * giou;
            Crow[j] = val;
        }
    }
}

// ---------------------------------------------------------------------------
// Transpose: C[b, q, b*T + t] -> g_ctr[b][t][q]
// ---------------------------------------------------------------------------
__global__ void transpose_kernel(const float* __restrict__ C)
{
    __shared__ float tile[32][33];
    const int b  = blockIdx.z;
    const int q0 = blockIdx.x * 32;
    const int t0 = blockIdx.y * 32;
    int q = q0 + threadIdx.y;
    int t = t0 + threadIdx.x;
    if (q < Q && t < TPB)
        tile[threadIdx.y][threadIdx.x] =
            C[((size_t)(b * Q + q)) * NT + (size_t)b * TPB + t];
    __syncthreads();
    int tt = t0 + threadIdx.y;
    int qq = q0 + threadIdx.x;
    if (tt < TPB && qq < Q)
        g_ctr[b * (TPB * Q) + tt * Q + qq] = tile[threadIdx.x][threadIdx.y];
}

// ---------------------------------------------------------------------------
// Order-preserving double <-> uint64 encoding (ascending), -0 canonicalized.
// ---------------------------------------------------------------------------
__device__ __forceinline__ unsigned long long enc64(double x)
{
    long long b = __double_as_longlong(x);
    if ((b << 1) == 0) b = 0;   // canonicalize -0.0 -> +0.0
    return (unsigned long long)(b ^ ((b >> 63) | 0x8000000000000000LL));
}
__device__ __forceinline__ double dec64(unsigned long long e)
{
    long long b = (long long)e;
    b ^= ((~b) >> 63) | 0x8000000000000000LL;
    return __longlong_as_double(b);
}

// ---------------------------------------------------------------------------
// Hungarian (JV shortest augmenting path), one block of 128 threads per batch.
// All comparisons in integer domain on encoded keys; fp64 only for the exact
// value arithmetic matching the reference. ONE __syncthreads per iteration.
// ---------------------------------------------------------------------------
#define K 8
__global__ void __launch_bounds__(128, 1) lsa_kernel(float* __restrict__ out)
{
    const int b = blockIdx.x;
    const int tid = threadIdx.x;          // 128; column j-1 = tid + k*128
    const int w = tid >> 5, lane = tid & 31;

    __shared__ double u[TPB + 2];
    __shared__ int    p[Q + 2];
    __shared__ int    way[Q + 2];
    __shared__ unsigned long long s_e[2][4];
    __shared__ int    s_jj[2][4];
    __shared__ int    ans[TPB];

    double v[K];
    int rowof[K];
#pragma unroll
    for (int k = 0; k < K; k++) { v[k] = 0.0; rowof[k] = 0; }

    for (int x = tid; x <= Q; x += 128) p[x] = 0;
    if (tid <= TPB) u[tid] = 0.0;
    __syncthreads();

    const float* cb = g_ctr + b * (TPB * Q);
    const unsigned long long ENC_INF = enc64(1e300);

    for (int i = 1; i <= TPB; i++) {
        if (tid == 0) p[0] = i;
        double minv[K];
        unsigned long long em[K];
        unsigned usedm = 0;
#pragma unroll
        for (int k = 0; k < K; k++) { minv[k] = 1e300; em[k] = ENC_INF; }

        int i0 = i, j0 = 0;
        double ui0 = 0.0;     // u[i] == 0 the first time row i is processed
        float r[K];
        {
            const float* crow = cb + (i0 - 1) * Q;
#pragma unroll
            for (int k = 0; k < K; k++) {
                int col = tid + k * 128;
                r[k] = (col < Q) ? __ldg(&crow[col]) : 0.0f;
            }
        }
        int par = 0;

        while (true) {
            // mark column chosen last step as used (owner thread)
            if (j0 >= 1) {
                int idx = j0 - 1;
                if ((idx & 127) == tid) {
                    usedm |= 1u << (idx >> 7);
                    rowof[idx >> 7] = i0;
                }
            }
            // scan my unused columns (fp64 arith, integer compares)
            unsigned long long bestE = ~0ULL; int bestJ = Q + 2;
#pragma unroll
            for (int k = 0; k < K; k++) {
                int col = tid + k * 128;
                if (col < Q && !((usedm >> k) & 1u)) {
                    double cur = ((double)r[k] - ui0) - v[k];
                    unsigned long long ce = enc64(cur);
                    if (ce < em[k]) { em[k] = ce; minv[k] = cur; way[col + 1] = j0; }
                    if (em[k] < bestE) { bestE = em[k]; bestJ = col + 1; }
                    else if (em[k] == bestE && col + 1 < bestJ) bestJ = col + 1;
                }
            }
            // warp butterfly (integer, ties -> smaller j)
            for (int o = 16; o; o >>= 1) {
                unsigned long long oe = __shfl_xor_sync(~0u, bestE, o);
                int oj = __shfl_xor_sync(~0u, bestJ, o);
                if (oe < bestE || (oe == bestE && oj < bestJ)) { bestE = oe; bestJ = oj; }
            }
            if (lane == 0) { s_e[par][w] = bestE; s_jj[par][w] = bestJ; }
            __syncthreads();                                   // ONE barrier

            // all threads: final 4-way reduce (integer)
            unsigned long long de = s_e[par][0]; int j1 = s_jj[par][0];
#pragma unroll
            for (int ww = 1; ww < 4; ww++) {
                unsigned long long e2 = s_e[par][ww]; int j2 = s_jj[par][ww];
                if (e2 < de || (e2 == de && j2 < j1)) { de = e2; j1 = j2; }
            }
            const double delta = dec64(de);
            const int i1 = p[j1];

            // prefetch next row + u[i1] (row i1 untouched by this iter's updates)
            float r2[K]; double unext = 0.0;
            if (i1 != 0) {
                const float* crow2 = cb + (i1 - 1) * Q;
#pragma unroll
                for (int k = 0; k < K; k++) {
                    int col = tid + k * 128;
                    r2[k] = (col < Q) ? __ldg(&crow2[col]) : 0.0f;
                }
                unext = u[i1];
            }

            // dual updates (reference order; exact fp64)
#pragma unroll
            for (int k = 0; k < K; k++) {
                int col = tid + k * 128;
                if (col < Q) {
                    if ((usedm >> k) & 1u) { v[k] -= delta; u[rowof[k]] += delta; }
                    else {
                        minv[k] -= delta;
                        em[k] = enc64(minv[k]);
                    }
                }
            }
            if (tid == 0) u[i] += delta;   // virtual column 0 (row i)

            if (i1 == 0) {
                if (tid == 0) {
                    int jj = j1;
                    while (jj) { int jp = way[jj]; p[jj] = p[jp]; jj = jp; }
                }
                break;   // path-walk ordered before next round by its first barrier
            }
            j0 = j1; i0 = i1; ui0 = unext;
#pragma unroll
            for (int k = 0; k < K; k++) r[k] = r2[k];
            par ^= 1;
        }
        __syncthreads();   // p[] path-walk visible before next round / epilogue
    }

    // ans[t] = matched prediction index for target t
#pragma unroll
    for (int k = 0; k < K; k++) {
        int j = tid + k * 128 + 1;
        if (j <= Q && p[j] > 0) ans[p[j] - 1] = j - 1;
    }
    __syncthreads();
    if (tid < TPB) {
        int a = ans[tid];
        int rank = 0;
        for (int t2 = 0; t2 < TPB; t2++) rank += (ans[t2] < a) ? 1 : 0;
        out[(size_t)C_ELEMS + (size_t)b * TPB + rank]                    = (float)a;
        out[(size_t)C_ELEMS + (size_t)BS * TPB + (size_t)b * TPB + rank] = (float)tid;
    }
}

// ---------------------------------------------------------------------------
extern "C" void kernel_launch(void* const* d_in, const int* in_sizes, int n_in,
                              void* d_out, int out_size)
{
    const float* logits = (const float*)d_in[0];
    const float* boxes  = (const float*)d_in[1];
    const void*  ids    = d_in[2];
    const float* tbox   = (const float*)d_in[3];
    float* out = (float*)d_out;

    detect_ids_kernel<<<1, 128>>>((const unsigned int*)ids);
    cost_kernel<<<(BS * Q) / QPB, 128>>>(logits, boxes, ids, tbox, out);
    dim3 tgrid((Q + 31) / 32, (TPB + 31) / 32, BS);
    transpose_kernel<<<tgrid, dim3(32, 32)>>>(out);
    lsa_kernel<<<BS, 128>>>(out);
}